// round 16
// baseline (speedup 1.0000x reference)
#include <cuda_runtime.h>
#include <cuda_fp16.h>
#include <cstdint>

// Problem constants
#define SS 4096
#define BB 8
#define EE 1024
#define HH 16
#define DD 64
#define PP 64
#define M_ROWS (SS * BB)        // 32768
#define N_FUSED (3 * EE)        // 3072

// ---------------- Scratch (static device globals) ---------------------------
__device__ __half g_xh[(size_t)M_ROWS * EE];            // x fp16
__device__ __half g_Wch[(size_t)N_FUSED * EE];          // combined weights fp16
__device__ __half g_qh[(size_t)M_ROWS * EE];            // q' fp16 (M x 1024)
__device__ __half g_kvh[(size_t)M_ROWS * 2 * EE];       // k'|v fp16 (M x 2048)
__device__ __half g_ah[(size_t)M_ROWS * EE];            // attn fp16
__device__ __half g_woh[(size_t)EE * EE];               // w_out fp16
__device__ float  g_kv[(size_t)HH * BB * PP * DD];      // 524288 floats
__device__ float  g_ksum[(size_t)HH * BB * PP];         // 8192 floats

// ---------------- helpers ----------------------------------------------------
__device__ __forceinline__ uint32_t smem_u32(const void* p) {
    uint32_t a;
    asm("{ .reg .u64 t; cvta.to.shared.u64 t, %1; cvt.u32.u64 %0, t; }"
        : "=r"(a) : "l"(p));
    return a;
}
__device__ __forceinline__ void cp16(uint32_t dst, const void* src) {
    asm volatile("cp.async.ca.shared.global [%0], [%1], 16;"
                 :: "r"(dst), "l"(src) : "memory");
}
#define CP_COMMIT() asm volatile("cp.async.commit_group;" ::: "memory")
#define CP_WAIT1()  asm volatile("cp.async.wait_group 1;" ::: "memory")

#define LDM4(r0, r1, r2, r3, addr) \
    asm volatile("ldmatrix.sync.aligned.m8n8.x4.shared.b16 {%0,%1,%2,%3}, [%4];" \
                 : "=r"(r0), "=r"(r1), "=r"(r2), "=r"(r3) : "r"(addr))

__device__ __forceinline__ void mma_f16(float* c, const uint32_t* a, const uint32_t* b) {
    asm volatile(
        "mma.sync.aligned.m16n8k16.row.col.f32.f16.f16.f32 "
        "{%0,%1,%2,%3}, {%4,%5,%6,%7}, {%8,%9}, {%0,%1,%2,%3};"
        : "+f"(c[0]), "+f"(c[1]), "+f"(c[2]), "+f"(c[3])
        : "r"(a[0]), "r"(a[1]), "r"(a[2]), "r"(a[3]), "r"(b[0]), "r"(b[1]));
}

// ---------------- Unified prep kernel ------------------------------------------
// blockIdx ranges:
//   [0, 2048):      combined q/k weights -> g_Wch (fp16)
//   [2048, 3072):   v weight copy -> g_Wch (fp16)
//   [3072, 11264):  convert x -> g_xh (8192 blocks x 1024 float4)
//   [11264, 12288): convert w_out -> g_woh (1024 blocks x 256 float4)
//   [12288, 12808): zero g_kv / g_ksum (520 blocks x 256 float4)
__global__ void __launch_bounds__(256)
prep_kernel(const float* __restrict__ x, const float* __restrict__ w_qkv,
            const float* __restrict__ w_out, const float* __restrict__ w_f) {
    int bi = blockIdx.x;
    int tid = threadIdx.x;

    if (bi < 2048) {
        int n = bi;
        int part = n >> 10;
        int h = (n & 1023) >> 6;
        int p = n & 63;
        __shared__ float wf[64];
        if (tid < 64) wf[tid] = w_f[p * 64 + tid];
        __syncthreads();
        float acc[4] = {0.f, 0.f, 0.f, 0.f};
        const float* src = w_qkv + (size_t)(part * 1024 + h * 64) * EE;
#pragma unroll 4
        for (int d = 0; d < 64; d++) {
            float w = wf[d];
#pragma unroll
            for (int i = 0; i < 4; i++)
                acc[i] += w * src[(size_t)d * EE + tid + i * 256];
        }
#pragma unroll
        for (int i = 0; i < 4; i++)
            g_Wch[(size_t)n * EE + tid + i * 256] = __float2half(acc[i]);
    } else if (bi < 3072) {
        int n = bi;   // v rows 2048..3071
        for (int e = tid; e < EE; e += 256)
            g_Wch[(size_t)n * EE + e] = __float2half(w_qkv[(size_t)n * EE + e]);
    } else if (bi < 11264) {
        // convert x: 8192 blocks x 1024 float4
        size_t base = (size_t)(bi - 3072) * 1024;
#pragma unroll
        for (int k = 0; k < 4; k++) {
            size_t i = base + k * 256 + tid;
            float4 v = reinterpret_cast<const float4*>(x)[i];
            __half2 a = __floats2half2_rn(v.x, v.y);
            __half2 b = __floats2half2_rn(v.z, v.w);
            uint2 o; o.x = *reinterpret_cast<uint32_t*>(&a);
            o.y = *reinterpret_cast<uint32_t*>(&b);
            reinterpret_cast<uint2*>(g_xh)[i] = o;
        }
    } else if (bi < 12288) {
        // convert w_out: 1024 blocks x 256 float4
        size_t i = (size_t)(bi - 11264) * 256 + tid;
        float4 v = reinterpret_cast<const float4*>(w_out)[i];
        __half2 a = __floats2half2_rn(v.x, v.y);
        __half2 b = __floats2half2_rn(v.z, v.w);
        uint2 o; o.x = *reinterpret_cast<uint32_t*>(&a);
        o.y = *reinterpret_cast<uint32_t*>(&b);
        reinterpret_cast<uint2*>(g_woh)[i] = o;
    } else {
        // zero kv/ksum: 520 blocks x 256 float4
        size_t i4 = (size_t)(bi - 12288) * 256 + tid;
        float4 z; z.x = 0.f; z.y = 0.f; z.z = 0.f; z.w = 0.f;
        if (i4 < 131072) {
            reinterpret_cast<float4*>(g_kv)[i4] = z;
        } else if (i4 < 133120) {
            reinterpret_cast<float4*>(g_ksum)[i4 - 131072] = z;
        }
    }
}

// ---------------- HMMA fp16 single-pass GEMM (2x2 warps, BK=64, 3 stages) ------
#define OP_BYTES  16384
#define N_STAGES  3
#define NOPS      2
#define STG_BYTES (NOPS * OP_BYTES)
#define HG_SMEM_BYTES (N_STAGES * STG_BYTES)

template <int EPI>
__global__ void __launch_bounds__(128, 2)
hgemm_kernel(const __half* __restrict__ A, const __half* __restrict__ B,
             float* __restrict__ C, __half* __restrict__ Cq, __half* __restrict__ Ckv,
             int M, int N, int K,
             const float* __restrict__ bias) {
    extern __shared__ uint32_t sm[];
    const int tid = threadIdx.x;
    const int lane = tid & 31, wid = tid >> 5;
    const int wm = wid >> 1, wn = wid & 1;      // 2 x 2 warp grid, 64x64 tiles
    const int gr = lane >> 2, qc = lane & 3;
    const int m0 = blockIdx.y * 128, n0 = blockIdx.x * 128;

    const __half* srcs[NOPS];
    srcs[0] = A + (size_t)m0 * K;
    srcs[1] = B + (size_t)n0 * K;

    const uint32_t smb = smem_u32(sm);

    const uint32_t sel = lane >> 3, rin = lane & 7;
    uint32_t a_lks[4], b_lks[4];
#pragma unroll
    for (int ks = 0; ks < 4; ks++) {
        uint32_t kta = ks * 2 + (sel >> 1);
        uint32_t ktb = ks * 2 + (sel & 1);
        a_lks[ks] = (sel & 1) * 1024 + (rin * 8 + ((kta + rin) & 7)) * 16;
        b_lks[ks] = (sel >> 1) * 1024 + (rin * 8 + ((ktb + rin) & 7)) * 16;
    }
    const uint32_t a_warp = (uint32_t)wm * 8192;
    const uint32_t b_warp = (uint32_t)wn * 8192;

    auto issue = [&](int stage, int k0) {
        uint32_t so = smb + (uint32_t)stage * STG_BYTES;
#pragma unroll
        for (int op = 0; op < NOPS; op++) {
#pragma unroll
            for (int i = 0; i < 8; i++) {
                int g = tid + i * 128;
                int row = g >> 3, c = g & 7;
                const __half* s = srcs[op] + (size_t)row * K + k0 + c * 8;
                uint32_t r = row & 7;
                uint32_t d = so + (uint32_t)op * OP_BYTES
                           + (uint32_t)(row >> 3) * 1024
                           + (r * 8 + (((uint32_t)c + r) & 7)) * 16;
                cp16(d, s);
            }
        }
        CP_COMMIT();
    };

    float acc[4][8][4];
#pragma unroll
    for (int i = 0; i < 4; i++)
#pragma unroll
        for (int j = 0; j < 8; j++)
#pragma unroll
            for (int q = 0; q < 4; q++) acc[i][j][q] = 0.f;

    const int nc = K >> 6;     // chunks of 64
    issue(0, 0);
    issue(1, 64);

    for (int ch = 0; ch < nc; ch++) {
        CP_WAIT1();
        __syncthreads();
        if (ch + 2 < nc) issue((ch + 2) % N_STAGES, (ch + 2) * 64);
        else CP_COMMIT();

        const uint32_t so = smb + (uint32_t)(ch % N_STAGES) * STG_BYTES;
#pragma unroll
        for (int ks = 0; ks < 4; ks++) {
            uint32_t a[4][4], b[8][2];
#pragma unroll
            for (int p = 0; p < 4; p++) {
                uint32_t ad = so + OP_BYTES + b_warp + (uint32_t)p * 2048 + b_lks[ks];
                LDM4(b[2 * p][0], b[2 * p][1], b[2 * p + 1][0], b[2 * p + 1][1], ad);
            }
#pragma unroll
            for (int mt = 0; mt < 4; mt++) {
                uint32_t ad = so + a_warp + (uint32_t)mt * 2048 + a_lks[ks];
                LDM4(a[mt][0], a[mt][1], a[mt][2], a[mt][3], ad);
            }
#pragma unroll
            for (int mt = 0; mt < 4; mt++)
#pragma unroll
                for (int nt = 0; nt < 8; nt++)
                    mma_f16(acc[mt][nt], a[mt], b[nt]);
        }
    }

    // Epilogue
#pragma unroll
    for (int mt = 0; mt < 4; mt++) {
#pragma unroll
        for (int nt = 0; nt < 8; nt++) {
            int row = m0 + wm * 64 + mt * 16 + gr;
            int col = n0 + wn * 64 + nt * 8 + qc * 2;
#pragma unroll
            for (int half = 0; half < 2; half++) {
                int r = row + half * 8;
                float v0 = acc[mt][nt][half * 2 + 0];
                float v1 = acc[mt][nt][half * 2 + 1];
                if (EPI == 1) {
                    if (col < 2048) {
                        v0 = fmaxf(v0 + bias[col & 63], 0.f);
                        v1 = fmaxf(v1 + bias[(col + 1) & 63], 0.f);
                    }
                    __half2 o = __floats2half2_rn(v0, v1);
                    if (col < 1024) {
                        *reinterpret_cast<__half2*>(Cq + (size_t)r * EE + col) = o;
                    } else {
                        *reinterpret_cast<__half2*>(Ckv + (size_t)r * 2048 + (col - 1024)) = o;
                    }
                } else {
                    v0 += bias[col];
                    v1 += bias[col + 1];
                    float2 o; o.x = v0; o.y = v1;
                    *reinterpret_cast<float2*>(C + (size_t)r * N + col) = o;
                }
            }
        }
    }
}

// ---------------- kv reduction (split-S x 8, fp16 input, float4 STS) -----------
__global__ void __launch_bounds__(256)
kv_kernel() {
    int hb = blockIdx.x;
    int split = blockIdx.y;
    int h = hb >> 3, b = hb & 7;

    __shared__ float kt[64][64];
    __shared__ float vt[64][64];

    int tid = threadIdx.x;
    int c8 = tid & 7;
    int r0 = tid >> 3;

    const __half* kbase = g_kvh + (size_t)b * 2048 + h * 64;
    const __half* vbase = g_kvh + (size_t)b * 2048 + 1024 + h * 64;

    float acc[4][4];
#pragma unroll
    for (int i = 0; i < 4; i++)
#pragma unroll
        for (int j = 0; j < 4; j++) acc[i][j] = 0.f;
    float ksacc[8];
#pragma unroll
    for (int l = 0; l < 8; l++) ksacc[l] = 0.f;

    int ty = tid >> 4, tx = tid & 15;
    int sbeg = split * 512;
    for (int s0 = sbeg; s0 < sbeg + 512; s0 += 64) {
#pragma unroll
        for (int i = 0; i < 2; i++) {
            int row = r0 + i * 32;
            size_t g = (size_t)(s0 + row) * BB * 2048;
            uint4 kraw = *(const uint4*)(kbase + g + c8 * 8);
            const __half2* kh = reinterpret_cast<const __half2*>(&kraw);
            float4 kf0, kf1;
            {
                float2 f0 = __half22float2(kh[0]);
                float2 f1 = __half22float2(kh[1]);
                float2 f2 = __half22float2(kh[2]);
                float2 f3 = __half22float2(kh[3]);
                kf0.x = f0.x; kf0.y = f0.y; kf0.z = f1.x; kf0.w = f1.y;
                kf1.x = f2.x; kf1.y = f2.y; kf1.z = f3.x; kf1.w = f3.y;
            }
            ksacc[0] += kf0.x; ksacc[1] += kf0.y; ksacc[2] += kf0.z; ksacc[3] += kf0.w;
            ksacc[4] += kf1.x; ksacc[5] += kf1.y; ksacc[6] += kf1.z; ksacc[7] += kf1.w;
            *(float4*)&kt[row][c8 * 8]     = kf0;
            *(float4*)&kt[row][c8 * 8 + 4] = kf1;

            uint4 vraw = *(const uint4*)(vbase + g + c8 * 8);
            const __half2* vh = reinterpret_cast<const __half2*>(&vraw);
            float4 vf0, vf1;
            {
                float2 f0 = __half22float2(vh[0]);
                float2 f1 = __half22float2(vh[1]);
                float2 f2 = __half22float2(vh[2]);
                float2 f3 = __half22float2(vh[3]);
                vf0.x = f0.x; vf0.y = f0.y; vf0.z = f1.x; vf0.w = f1.y;
                vf1.x = f2.x; vf1.y = f2.y; vf1.z = f3.x; vf1.w = f3.y;
            }
            *(float4*)&vt[row][c8 * 8]     = vf0;
            *(float4*)&vt[row][c8 * 8 + 4] = vf1;
        }
        __syncthreads();
#pragma unroll 8
        for (int ss = 0; ss < 64; ss++) {
            float4 a = *(const float4*)&kt[ss][ty * 4];
            float4 c = *(const float4*)&vt[ss][tx * 4];
            float av[4] = {a.x, a.y, a.z, a.w};
            float cv[4] = {c.x, c.y, c.z, c.w};
#pragma unroll
            for (int i = 0; i < 4; i++)
#pragma unroll
                for (int j = 0; j < 4; j++)
                    acc[i][j] += av[i] * cv[j];
        }
        __syncthreads();
    }

    float* kvb = g_kv + (size_t)hb * (PP * DD);
#pragma unroll
    for (int i = 0; i < 4; i++)
#pragma unroll
        for (int j = 0; j < 4; j++)
            atomicAdd(&kvb[(ty * 4 + i) * 64 + tx * 4 + j], acc[i][j]);
#pragma unroll
    for (int l = 0; l < 8; l++)
        atomicAdd(&g_ksum[hb * 64 + c8 * 8 + l], ksacc[l]);
}

// ---------------- attention + normalization (row-major threads, float4 kv) -----
// Thread t -> row r = t>>4 (16 rows/iter), d-quad dq = (t&15)*4.
// Inner loop per p: 1 broadcast LDS (q) + 1 LDS.128 (kv) + 4 FMA.
// den computed once per row (dedup from R15).
__global__ void __launch_bounds__(256)
attn_kernel() {
    int chunk = blockIdx.x;           // 128 s-rows per block
    int hb = blockIdx.y;
    int h = hb >> 3, b = hb & 7;

    __shared__ float kvs[64][64];
    __shared__ float kss[64];
    __shared__ float qs[16][64];
    __shared__ float dpart[16][5];
    __shared__ float dens[16];

    int tid = threadIdx.x;
    for (int i = tid; i < 4096; i += 256)
        kvs[i >> 6][i & 63] = g_kv[(size_t)hb * 4096 + i];
    if (tid < 64) kss[tid] = g_ksum[hb * 64 + tid];
    __syncthreads();

    int r  = tid >> 4;                // 0..15 (row, load + compute)
    int lq = tid & 15;                // quad index
    int dq = lq * 4;                  // d base

    for (int it = 0; it < 8; it++) {
        int sbase = chunk * 128 + it * 16;
        // load 16 q' rows (fp16 -> fp32 smem, float4 store)
        {
            size_t row = ((size_t)(sbase + r) * BB + b) * EE;
            uint2 raw = *reinterpret_cast<const uint2*>(g_qh + row + h * 64 + dq);
            const __half2* qh = reinterpret_cast<const __half2*>(&raw);
            float2 f0 = __half22float2(qh[0]);
            float2 f1 = __half22float2(qh[1]);
            float4 qf; qf.x = f0.x; qf.y = f0.y; qf.z = f1.x; qf.w = f1.y;
            *(float4*)&qs[r][dq] = qf;
        }
        __syncthreads();

        // den partials: threads 0..63, row rr = tid>>2, p-segment seg = tid&3
        if (tid < 64) {
            int rr = tid >> 2, seg = tid & 3;
            float dn = 0.f;
#pragma unroll
            for (int pp = 0; pp < 16; pp++) {
                int p = seg * 16 + pp;
                dn += qs[rr][p] * kss[p];
            }
            dpart[rr][seg] = dn;
        }

        // num: 1 row x 4 d per thread
        float num[4] = {0.f, 0.f, 0.f, 0.f};
#pragma unroll
        for (int p = 0; p < 64; p++) {
            float qv = qs[r][p];
            float4 kvv = *(const float4*)&kvs[p][dq];
            num[0] += qv * kvv.x;
            num[1] += qv * kvv.y;
            num[2] += qv * kvv.z;
            num[3] += qv * kvv.w;
        }
        __syncthreads();

        if (tid < 16)
            dens[tid] = dpart[tid][0] + dpart[tid][1] + dpart[tid][2] + dpart[tid][3];
        __syncthreads();

        {
            float inv = 1.0f / (dens[r] + 1e-8f);
            __half2 o0 = __floats2half2_rn(num[0] * inv, num[1] * inv);
            __half2 o1 = __floats2half2_rn(num[2] * inv, num[3] * inv);
            uint2 o; o.x = *reinterpret_cast<uint32_t*>(&o0);
            o.y = *reinterpret_cast<uint32_t*>(&o1);
            int s = sbase + r;
            *reinterpret_cast<uint2*>(g_ah + ((size_t)s * BB + b) * EE + h * 64 + dq) = o;
        }
        __syncthreads();
    }
}

// ---------------- Launch -------------------------------------------------------
extern "C" void kernel_launch(void* const* d_in, const int* in_sizes, int n_in,
                              void* d_out, int out_size) {
    const float* x      = (const float*)d_in[0];
    const float* w_qkv  = (const float*)d_in[1];
    const float* w_out  = (const float*)d_in[2];
    const float* b_out  = (const float*)d_in[3];
    const float* w_f    = (const float*)d_in[4];
    const float* b_f    = (const float*)d_in[5];
    float* out = (float*)d_out;

    __half *xh, *wch, *qh, *kvh, *ah, *woh;
    cudaGetSymbolAddress((void**)&xh, g_xh);
    cudaGetSymbolAddress((void**)&wch, g_Wch);
    cudaGetSymbolAddress((void**)&qh, g_qh);
    cudaGetSymbolAddress((void**)&kvh, g_kvh);
    cudaGetSymbolAddress((void**)&ah, g_ah);
    cudaGetSymbolAddress((void**)&woh, g_woh);

    cudaFuncSetAttribute((const void*)hgemm_kernel<1>,
                         cudaFuncAttributeMaxDynamicSharedMemorySize, HG_SMEM_BYTES);
    cudaFuncSetAttribute((const void*)hgemm_kernel<2>,
                         cudaFuncAttributeMaxDynamicSharedMemorySize, HG_SMEM_BYTES);

    // 1. unified prep: combined weights + x/w_out conversion + kv/ksum zero
    prep_kernel<<<12808, 256>>>(x, w_qkv, w_out, w_f);

    // 2. fused qkv+featuremap GEMM: fp16 single-pass, BK=64, split fp16 output
    hgemm_kernel<1><<<dim3(N_FUSED / 128, M_ROWS / 128), 128, HG_SMEM_BYTES>>>(
        xh, wch, nullptr, qh, kvh, M_ROWS, N_FUSED, EE, b_f);

    // 3. kv / ksum reduction
    kv_kernel<<<dim3(HH * BB, 8), 256>>>();

    // 4. attention + normalization (row-major threads)
    attn_kernel<<<dim3(SS / 128, HH * BB), 256>>>();

    // 5. output projection: fp16 single-pass, BK=64, fp32 output
    hgemm_kernel<2><<<dim3(EE / 128, M_ROWS / 128), 128, HG_SMEM_BYTES>>>(
        ah, woh, out, nullptr, nullptr, M_ROWS, EE, EE, b_out);
}

// round 17
// speedup vs baseline: 1.0594x; 1.0594x over previous
#include <cuda_runtime.h>
#include <cuda_fp16.h>
#include <cstdint>

// Problem constants
#define SS 4096
#define BB 8
#define EE 1024
#define HH 16
#define DD 64
#define PP 64
#define M_ROWS (SS * BB)        // 32768
#define N_FUSED (3 * EE)        // 3072

// ---------------- Scratch (static device globals) ---------------------------
__device__ __half g_xh[(size_t)M_ROWS * EE];            // x fp16
__device__ __half g_Wch[(size_t)N_FUSED * EE];          // combined weights fp16
__device__ __half g_qh[(size_t)M_ROWS * EE];            // q' fp16 (M x 1024)
__device__ __half g_kvh[(size_t)M_ROWS * 2 * EE];       // k'|v fp16 (M x 2048)
__device__ __half g_ah[(size_t)M_ROWS * EE];            // attn fp16
__device__ __half g_woh[(size_t)EE * EE];               // w_out fp16
__device__ float  g_kv[(size_t)HH * BB * PP * DD];      // 524288 floats
__device__ float  g_ksum[(size_t)HH * BB * PP];         // 8192 floats

// ---------------- helpers ----------------------------------------------------
__device__ __forceinline__ uint32_t smem_u32(const void* p) {
    uint32_t a;
    asm("{ .reg .u64 t; cvta.to.shared.u64 t, %1; cvt.u32.u64 %0, t; }"
        : "=r"(a) : "l"(p));
    return a;
}
__device__ __forceinline__ void cp16(uint32_t dst, const void* src) {
    asm volatile("cp.async.ca.shared.global [%0], [%1], 16;"
                 :: "r"(dst), "l"(src) : "memory");
}
#define CP_COMMIT() asm volatile("cp.async.commit_group;" ::: "memory")
#define CP_WAIT1()  asm volatile("cp.async.wait_group 1;" ::: "memory")

#define LDM4(r0, r1, r2, r3, addr) \
    asm volatile("ldmatrix.sync.aligned.m8n8.x4.shared.b16 {%0,%1,%2,%3}, [%4];" \
                 : "=r"(r0), "=r"(r1), "=r"(r2), "=r"(r3) : "r"(addr))

__device__ __forceinline__ void mma_f16(float* c, const uint32_t* a, const uint32_t* b) {
    asm volatile(
        "mma.sync.aligned.m16n8k16.row.col.f32.f16.f16.f32 "
        "{%0,%1,%2,%3}, {%4,%5,%6,%7}, {%8,%9}, {%0,%1,%2,%3};"
        : "+f"(c[0]), "+f"(c[1]), "+f"(c[2]), "+f"(c[3])
        : "r"(a[0]), "r"(a[1]), "r"(a[2]), "r"(a[3]), "r"(b[0]), "r"(b[1]));
}

// ---------------- Unified prep kernel ------------------------------------------
// blockIdx ranges:
//   [0, 2048):      combined q/k weights -> g_Wch (fp16)
//   [2048, 3072):   v weight copy -> g_Wch (fp16)
//   [3072, 11264):  convert x -> g_xh (8192 blocks x 1024 float4)
//   [11264, 12288): convert w_out -> g_woh (1024 blocks x 256 float4)
//   [12288, 12808): zero g_kv / g_ksum (520 blocks x 256 float4)
__global__ void __launch_bounds__(256)
prep_kernel(const float* __restrict__ x, const float* __restrict__ w_qkv,
            const float* __restrict__ w_out, const float* __restrict__ w_f) {
    int bi = blockIdx.x;
    int tid = threadIdx.x;

    if (bi < 2048) {
        int n = bi;
        int part = n >> 10;
        int h = (n & 1023) >> 6;
        int p = n & 63;
        __shared__ float wf[64];
        if (tid < 64) wf[tid] = w_f[p * 64 + tid];
        __syncthreads();
        float acc[4] = {0.f, 0.f, 0.f, 0.f};
        const float* src = w_qkv + (size_t)(part * 1024 + h * 64) * EE;
#pragma unroll 4
        for (int d = 0; d < 64; d++) {
            float w = wf[d];
#pragma unroll
            for (int i = 0; i < 4; i++)
                acc[i] += w * src[(size_t)d * EE + tid + i * 256];
        }
#pragma unroll
        for (int i = 0; i < 4; i++)
            g_Wch[(size_t)n * EE + tid + i * 256] = __float2half(acc[i]);
    } else if (bi < 3072) {
        int n = bi;   // v rows 2048..3071
        for (int e = tid; e < EE; e += 256)
            g_Wch[(size_t)n * EE + e] = __float2half(w_qkv[(size_t)n * EE + e]);
    } else if (bi < 11264) {
        // convert x: 8192 blocks x 1024 float4
        size_t base = (size_t)(bi - 3072) * 1024;
#pragma unroll
        for (int k = 0; k < 4; k++) {
            size_t i = base + k * 256 + tid;
            float4 v = reinterpret_cast<const float4*>(x)[i];
            __half2 a = __floats2half2_rn(v.x, v.y);
            __half2 b = __floats2half2_rn(v.z, v.w);
            uint2 o; o.x = *reinterpret_cast<uint32_t*>(&a);
            o.y = *reinterpret_cast<uint32_t*>(&b);
            reinterpret_cast<uint2*>(g_xh)[i] = o;
        }
    } else if (bi < 12288) {
        // convert w_out: 1024 blocks x 256 float4
        size_t i = (size_t)(bi - 11264) * 256 + tid;
        float4 v = reinterpret_cast<const float4*>(w_out)[i];
        __half2 a = __floats2half2_rn(v.x, v.y);
        __half2 b = __floats2half2_rn(v.z, v.w);
        uint2 o; o.x = *reinterpret_cast<uint32_t*>(&a);
        o.y = *reinterpret_cast<uint32_t*>(&b);
        reinterpret_cast<uint2*>(g_woh)[i] = o;
    } else {
        // zero kv/ksum: 520 blocks x 256 float4
        size_t i4 = (size_t)(bi - 12288) * 256 + tid;
        float4 z; z.x = 0.f; z.y = 0.f; z.z = 0.f; z.w = 0.f;
        if (i4 < 131072) {
            reinterpret_cast<float4*>(g_kv)[i4] = z;
        } else if (i4 < 133120) {
            reinterpret_cast<float4*>(g_ksum)[i4 - 131072] = z;
        }
    }
}

// ---------------- HMMA fp16 single-pass GEMM (2x2 warps, BK=64, 3 stages) ------
#define OP_BYTES  16384
#define N_STAGES  3
#define NOPS      2
#define STG_BYTES (NOPS * OP_BYTES)
#define HG_SMEM_BYTES (N_STAGES * STG_BYTES)

template <int EPI>
__global__ void __launch_bounds__(128, 2)
hgemm_kernel(const __half* __restrict__ A, const __half* __restrict__ B,
             float* __restrict__ C, __half* __restrict__ Cq, __half* __restrict__ Ckv,
             int M, int N, int K,
             const float* __restrict__ bias) {
    extern __shared__ uint32_t sm[];
    const int tid = threadIdx.x;
    const int lane = tid & 31, wid = tid >> 5;
    const int wm = wid >> 1, wn = wid & 1;      // 2 x 2 warp grid, 64x64 tiles
    const int gr = lane >> 2, qc = lane & 3;
    const int m0 = blockIdx.y * 128, n0 = blockIdx.x * 128;

    const __half* srcs[NOPS];
    srcs[0] = A + (size_t)m0 * K;
    srcs[1] = B + (size_t)n0 * K;

    const uint32_t smb = smem_u32(sm);

    const uint32_t sel = lane >> 3, rin = lane & 7;
    uint32_t a_lks[4], b_lks[4];
#pragma unroll
    for (int ks = 0; ks < 4; ks++) {
        uint32_t kta = ks * 2 + (sel >> 1);
        uint32_t ktb = ks * 2 + (sel & 1);
        a_lks[ks] = (sel & 1) * 1024 + (rin * 8 + ((kta + rin) & 7)) * 16;
        b_lks[ks] = (sel >> 1) * 1024 + (rin * 8 + ((ktb + rin) & 7)) * 16;
    }
    const uint32_t a_warp = (uint32_t)wm * 8192;
    const uint32_t b_warp = (uint32_t)wn * 8192;

    auto issue = [&](int stage, int k0) {
        uint32_t so = smb + (uint32_t)stage * STG_BYTES;
#pragma unroll
        for (int op = 0; op < NOPS; op++) {
#pragma unroll
            for (int i = 0; i < 8; i++) {
                int g = tid + i * 128;
                int row = g >> 3, c = g & 7;
                const __half* s = srcs[op] + (size_t)row * K + k0 + c * 8;
                uint32_t r = row & 7;
                uint32_t d = so + (uint32_t)op * OP_BYTES
                           + (uint32_t)(row >> 3) * 1024
                           + (r * 8 + (((uint32_t)c + r) & 7)) * 16;
                cp16(d, s);
            }
        }
        CP_COMMIT();
    };

    float acc[4][8][4];
#pragma unroll
    for (int i = 0; i < 4; i++)
#pragma unroll
        for (int j = 0; j < 8; j++)
#pragma unroll
            for (int q = 0; q < 4; q++) acc[i][j][q] = 0.f;

    const int nc = K >> 6;     // chunks of 64
    issue(0, 0);
    issue(1, 64);

    for (int ch = 0; ch < nc; ch++) {
        CP_WAIT1();
        __syncthreads();
        if (ch + 2 < nc) issue((ch + 2) % N_STAGES, (ch + 2) * 64);
        else CP_COMMIT();

        const uint32_t so = smb + (uint32_t)(ch % N_STAGES) * STG_BYTES;
#pragma unroll
        for (int ks = 0; ks < 4; ks++) {
            uint32_t a[4][4], b[8][2];
#pragma unroll
            for (int p = 0; p < 4; p++) {
                uint32_t ad = so + OP_BYTES + b_warp + (uint32_t)p * 2048 + b_lks[ks];
                LDM4(b[2 * p][0], b[2 * p][1], b[2 * p + 1][0], b[2 * p + 1][1], ad);
            }
#pragma unroll
            for (int mt = 0; mt < 4; mt++) {
                uint32_t ad = so + a_warp + (uint32_t)mt * 2048 + a_lks[ks];
                LDM4(a[mt][0], a[mt][1], a[mt][2], a[mt][3], ad);
            }
#pragma unroll
            for (int mt = 0; mt < 4; mt++)
#pragma unroll
                for (int nt = 0; nt < 8; nt++)
                    mma_f16(acc[mt][nt], a[mt], b[nt]);
        }
    }

    // Epilogue
#pragma unroll
    for (int mt = 0; mt < 4; mt++) {
#pragma unroll
        for (int nt = 0; nt < 8; nt++) {
            int row = m0 + wm * 64 + mt * 16 + gr;
            int col = n0 + wn * 64 + nt * 8 + qc * 2;
#pragma unroll
            for (int half = 0; half < 2; half++) {
                int r = row + half * 8;
                float v0 = acc[mt][nt][half * 2 + 0];
                float v1 = acc[mt][nt][half * 2 + 1];
                if (EPI == 1) {
                    if (col < 2048) {
                        v0 = fmaxf(v0 + bias[col & 63], 0.f);
                        v1 = fmaxf(v1 + bias[(col + 1) & 63], 0.f);
                    }
                    __half2 o = __floats2half2_rn(v0, v1);
                    if (col < 1024) {
                        *reinterpret_cast<__half2*>(Cq + (size_t)r * EE + col) = o;
                    } else {
                        *reinterpret_cast<__half2*>(Ckv + (size_t)r * 2048 + (col - 1024)) = o;
                    }
                } else {
                    v0 += bias[col];
                    v1 += bias[col + 1];
                    float2 o; o.x = v0; o.y = v1;
                    *reinterpret_cast<float2*>(C + (size_t)r * N + col) = o;
                }
            }
        }
    }
}

// ---------------- kv reduction (split-S x 8, fp16 input, float4 STS) -----------
__global__ void __launch_bounds__(256)
kv_kernel() {
    int hb = blockIdx.x;
    int split = blockIdx.y;
    int h = hb >> 3, b = hb & 7;

    __shared__ float kt[64][64];
    __shared__ float vt[64][64];

    int tid = threadIdx.x;
    int c8 = tid & 7;
    int r0 = tid >> 3;

    const __half* kbase = g_kvh + (size_t)b * 2048 + h * 64;
    const __half* vbase = g_kvh + (size_t)b * 2048 + 1024 + h * 64;

    float acc[4][4];
#pragma unroll
    for (int i = 0; i < 4; i++)
#pragma unroll
        for (int j = 0; j < 4; j++) acc[i][j] = 0.f;
    float ksacc[8];
#pragma unroll
    for (int l = 0; l < 8; l++) ksacc[l] = 0.f;

    int ty = tid >> 4, tx = tid & 15;
    int sbeg = split * 512;
    for (int s0 = sbeg; s0 < sbeg + 512; s0 += 64) {
#pragma unroll
        for (int i = 0; i < 2; i++) {
            int row = r0 + i * 32;
            size_t g = (size_t)(s0 + row) * BB * 2048;
            uint4 kraw = *(const uint4*)(kbase + g + c8 * 8);
            const __half2* kh = reinterpret_cast<const __half2*>(&kraw);
            float4 kf0, kf1;
            {
                float2 f0 = __half22float2(kh[0]);
                float2 f1 = __half22float2(kh[1]);
                float2 f2 = __half22float2(kh[2]);
                float2 f3 = __half22float2(kh[3]);
                kf0.x = f0.x; kf0.y = f0.y; kf0.z = f1.x; kf0.w = f1.y;
                kf1.x = f2.x; kf1.y = f2.y; kf1.z = f3.x; kf1.w = f3.y;
            }
            ksacc[0] += kf0.x; ksacc[1] += kf0.y; ksacc[2] += kf0.z; ksacc[3] += kf0.w;
            ksacc[4] += kf1.x; ksacc[5] += kf1.y; ksacc[6] += kf1.z; ksacc[7] += kf1.w;
            *(float4*)&kt[row][c8 * 8]     = kf0;
            *(float4*)&kt[row][c8 * 8 + 4] = kf1;

            uint4 vraw = *(const uint4*)(vbase + g + c8 * 8);
            const __half2* vh = reinterpret_cast<const __half2*>(&vraw);
            float4 vf0, vf1;
            {
                float2 f0 = __half22float2(vh[0]);
                float2 f1 = __half22float2(vh[1]);
                float2 f2 = __half22float2(vh[2]);
                float2 f3 = __half22float2(vh[3]);
                vf0.x = f0.x; vf0.y = f0.y; vf0.z = f1.x; vf0.w = f1.y;
                vf1.x = f2.x; vf1.y = f2.y; vf1.z = f3.x; vf1.w = f3.y;
            }
            *(float4*)&vt[row][c8 * 8]     = vf0;
            *(float4*)&vt[row][c8 * 8 + 4] = vf1;
        }
        __syncthreads();
#pragma unroll 8
        for (int ss = 0; ss < 64; ss++) {
            float4 a = *(const float4*)&kt[ss][ty * 4];
            float4 c = *(const float4*)&vt[ss][tx * 4];
            float av[4] = {a.x, a.y, a.z, a.w};
            float cv[4] = {c.x, c.y, c.z, c.w};
#pragma unroll
            for (int i = 0; i < 4; i++)
#pragma unroll
                for (int j = 0; j < 4; j++)
                    acc[i][j] += av[i] * cv[j];
        }
        __syncthreads();
    }

    float* kvb = g_kv + (size_t)hb * (PP * DD);
#pragma unroll
    for (int i = 0; i < 4; i++)
#pragma unroll
        for (int j = 0; j < 4; j++)
            atomicAdd(&kvb[(ty * 4 + i) * 64 + tx * 4 + j], acc[i][j]);
#pragma unroll
    for (int l = 0; l < 8; l++)
        atomicAdd(&g_ksum[hb * 64 + c8 * 8 + l], ksacc[l]);
}

// ---------------- attention + normalization (R15 proven: den dedup) ------------
// num: all 256 threads, 4 rows x 1 d each; kv load = lane-indexed scalar
// (1 wavefront/warp), q loads broadcast — 51 FMA/wavefront.
// den: computed once per row (64 threads x 16-p partials + 16-thread reduce).
__global__ void __launch_bounds__(256)
attn_kernel() {
    int chunk = blockIdx.x;           // 128 s-rows per block
    int hb = blockIdx.y;
    int h = hb >> 3, b = hb & 7;

    __shared__ float kvs[64][64];
    __shared__ float kss[64];
    __shared__ float qs[16][64];
    __shared__ float dpart[16][5];
    __shared__ float dens[16];

    int tid = threadIdx.x;
    for (int i = tid; i < 4096; i += 256)
        kvs[i >> 6][i & 63] = g_kv[(size_t)hb * 4096 + i];
    if (tid < 64) kss[tid] = g_ksum[hb * 64 + tid];
    __syncthreads();

    int lrow = tid >> 4;              // 0..15 load row
    int lq   = tid & 15;              // quad (4 halves)
    int g = tid >> 6;                 // 0..3 compute group
    int d = tid & 63;

    for (int it = 0; it < 8; it++) {
        int sbase = chunk * 128 + it * 16;
        // load 16 q' rows (fp16 -> fp32 smem, float4 store)
        {
            size_t row = ((size_t)(sbase + lrow) * BB + b) * EE;
            uint2 raw = *reinterpret_cast<const uint2*>(g_qh + row + h * 64 + lq * 4);
            const __half2* qh = reinterpret_cast<const __half2*>(&raw);
            float2 f0 = __half22float2(qh[0]);
            float2 f1 = __half22float2(qh[1]);
            float4 qf; qf.x = f0.x; qf.y = f0.y; qf.z = f1.x; qf.w = f1.y;
            *(float4*)&qs[lrow][lq * 4] = qf;
        }
        __syncthreads();

        // den partials: threads 0..63, row r = tid>>2, p-segment seg = tid&3
        if (tid < 64) {
            int r = tid >> 2, seg = tid & 3;
            float dn = 0.f;
#pragma unroll
            for (int pp = 0; pp < 16; pp++) {
                int p = seg * 16 + pp;
                dn += qs[r][p] * kss[p];
            }
            dpart[r][seg] = dn;
        }

        // num: 4 rows per thread, no den in the loop
        float num[4] = {0.f, 0.f, 0.f, 0.f};
#pragma unroll
        for (int p = 0; p < 64; p++) {
            float kvv = kvs[p][d];
#pragma unroll
            for (int j = 0; j < 4; j++)
                num[j] += qs[j * 4 + g][p] * kvv;
        }
        __syncthreads();

        if (tid < 16)
            dens[tid] = dpart[tid][0] + dpart[tid][1] + dpart[tid][2] + dpart[tid][3];
        __syncthreads();

#pragma unroll
        for (int j = 0; j < 4; j++) {
            int r = j * 4 + g;
            int s = sbase + r;
            g_ah[((size_t)s * BB + b) * EE + h * 64 + d] =
                __float2half(num[j] / (dens[r] + 1e-8f));
        }
        __syncthreads();
    }
}

// ---------------- Launch -------------------------------------------------------
extern "C" void kernel_launch(void* const* d_in, const int* in_sizes, int n_in,
                              void* d_out, int out_size) {
    const float* x      = (const float*)d_in[0];
    const float* w_qkv  = (const float*)d_in[1];
    const float* w_out  = (const float*)d_in[2];
    const float* b_out  = (const float*)d_in[3];
    const float* w_f    = (const float*)d_in[4];
    const float* b_f    = (const float*)d_in[5];
    float* out = (float*)d_out;

    __half *xh, *wch, *qh, *kvh, *ah, *woh;
    cudaGetSymbolAddress((void**)&xh, g_xh);
    cudaGetSymbolAddress((void**)&wch, g_Wch);
    cudaGetSymbolAddress((void**)&qh, g_qh);
    cudaGetSymbolAddress((void**)&kvh, g_kvh);
    cudaGetSymbolAddress((void**)&ah, g_ah);
    cudaGetSymbolAddress((void**)&woh, g_woh);

    cudaFuncSetAttribute((const void*)hgemm_kernel<1>,
                         cudaFuncAttributeMaxDynamicSharedMemorySize, HG_SMEM_BYTES);
    cudaFuncSetAttribute((const void*)hgemm_kernel<2>,
                         cudaFuncAttributeMaxDynamicSharedMemorySize, HG_SMEM_BYTES);

    // 1. unified prep: combined weights + x/w_out conversion + kv/ksum zero
    prep_kernel<<<12808, 256>>>(x, w_qkv, w_out, w_f);

    // 2. fused qkv+featuremap GEMM: fp16 single-pass, BK=64, split fp16 output
    hgemm_kernel<1><<<dim3(N_FUSED / 128, M_ROWS / 128), 128, HG_SMEM_BYTES>>>(
        xh, wch, nullptr, qh, kvh, M_ROWS, N_FUSED, EE, b_f);

    // 3. kv / ksum reduction
    kv_kernel<<<dim3(HH * BB, 8), 256>>>();

    // 4. attention + normalization (R15 proven form)
    attn_kernel<<<dim3(SS / 128, HH * BB), 256>>>();

    // 5. output projection: fp16 single-pass, BK=64, fp32 output
    hgemm_kernel<2><<<dim3(EE / 128, M_ROWS / 128), 128, HG_SMEM_BYTES>>>(
        ah, woh, out, nullptr, nullptr, M_ROWS, EE, EE, b_out);
}